// round 12
// baseline (speedup 1.0000x reference)
#include <cuda_runtime.h>
#include <cuda_bf16.h>
#include <cstdint>

#define TTOK 16384
#define DDIM 512
#define KCB  16384

// ---------------- scratch (device globals: no allocation allowed) ----------
__device__ float g_res [TTOK * DDIM];
__device__ float g_qsum[TTOK * DDIM];
__device__ float g_csq [KCB];
__device__ int   g_idx [TTOK];
__device__ signed char g_res_i8[TTOK * DDIM];
__device__ signed char g_cb_i8 [KCB * DDIM];
__device__ float g_inv_sr[TTOK];
__device__ float g_inv_sc[KCB];
__device__ __nv_bfloat16 g_a_hi[TTOK * DDIM];   // activation hi/lo for enc/dec GEMM
__device__ __nv_bfloat16 g_a_lo[TTOK * DDIM];
__device__ __nv_bfloat16 g_w_hi[DDIM * DDIM];   // weight hi/lo
__device__ __nv_bfloat16 g_w_lo[DDIM * DDIM];
__device__ int g_cand[8][TTOK];

// ---------------- helpers ---------------------------------------------------
__device__ __forceinline__ unsigned fkey(float f) {
    unsigned u = __float_as_uint(f);
    return (u & 0x80000000u) ? ~u : (u | 0x80000000u);
}
__device__ __forceinline__ uint32_t swz(uint32_t off) {      // SW128 (Swizzle<3,4,3>)
    return off ^ (((off >> 7) & 7u) << 4);
}
__device__ __forceinline__ uint32_t smem_u32(const void* p) {
    uint32_t a;
    asm("{ .reg .u64 t; cvta.to.shared.u64 t, %1; cvt.u32.u64 %0, t; }"
        : "=r"(a) : "l"(p));
    return a;
}
__device__ __forceinline__ void cp16(uint32_t dst, const void* src) {
    asm volatile("cp.async.cg.shared.global [%0], [%1], 16;" :: "r"(dst), "l"(src));
}
#define CP_COMMIT()  asm volatile("cp.async.commit_group;" ::: "memory")
#define CP_WAIT(N)   asm volatile("cp.async.wait_group %0;" :: "n"(N) : "memory")

__device__ __forceinline__ void ldsm_x4(uint32_t& r0, uint32_t& r1,
                                        uint32_t& r2, uint32_t& r3, uint32_t a) {
    asm volatile("ldmatrix.sync.aligned.m8n8.x4.shared.b16 {%0,%1,%2,%3}, [%4];"
                 : "=r"(r0), "=r"(r1), "=r"(r2), "=r"(r3) : "r"(a));
}
__device__ __forceinline__ void ldsm_x2(uint32_t& r0, uint32_t& r1, uint32_t a) {
    asm volatile("ldmatrix.sync.aligned.m8n8.x2.shared.b16 {%0,%1}, [%2];"
                 : "=r"(r0), "=r"(r1) : "r"(a));
}
__device__ __forceinline__ void mma16816(float* c, const uint32_t* a,
                                         uint32_t b0, uint32_t b1) {
    asm volatile(
        "mma.sync.aligned.m16n8k16.row.col.f32.bf16.bf16.f32 "
        "{%0,%1,%2,%3}, {%4,%5,%6,%7}, {%8,%9}, {%0,%1,%2,%3};"
        : "+f"(c[0]), "+f"(c[1]), "+f"(c[2]), "+f"(c[3])
        : "r"(a[0]), "r"(a[1]), "r"(a[2]), "r"(a[3]), "r"(b0), "r"(b1));
}
// int8 tensor op: s32 += s8 x s8, m16n8k32. Fragment byte layout matches
// ldmatrix.b16 x4/x2 over the same bytes (16B tiles), so addressing is shared.
__device__ __forceinline__ void mma16832(int* c, const uint32_t* a,
                                         uint32_t b0, uint32_t b1) {
    asm volatile(
        "mma.sync.aligned.m16n8k32.row.col.s32.s8.s8.s32 "
        "{%0,%1,%2,%3}, {%4,%5,%6,%7}, {%8,%9}, {%0,%1,%2,%3};"
        : "+r"(c[0]), "+r"(c[1]), "+r"(c[2]), "+r"(c[3])
        : "r"(a[0]), "r"(a[1]), "r"(a[2]), "r"(a[3]), "r"(b0), "r"(b1));
}
__device__ __forceinline__ void ins3(unsigned long long* t, unsigned long long k) {
    if (k < t[2]) {
        if (k < t[1]) {
            t[2] = t[1];
            if (k < t[0]) { t[1] = t[0]; t[0] = k; } else t[1] = k;
        } else t[2] = k;
    }
}
__device__ __forceinline__ unsigned long long pk(float d, int idx) {
    return ((unsigned long long)fkey(d) << 32) | (unsigned)idx;
}

// ---------------- ||c||^2 ---------------------------------------------------
__global__ void csq_kernel(const float* __restrict__ C) {
    int row  = blockIdx.x * 8 + (threadIdx.x >> 5);
    int lane = threadIdx.x & 31;
    const float4* p = (const float4*)(C + (size_t)row * DDIM);
    float s = 0.f;
#pragma unroll
    for (int i = 0; i < 4; i++) {
        float4 v = p[lane + (i << 5)];
        s = fmaf(v.x, v.x, s); s = fmaf(v.y, v.y, s);
        s = fmaf(v.z, v.z, s); s = fmaf(v.w, v.w, s);
    }
#pragma unroll
    for (int o = 16; o; o >>= 1) s += __shfl_xor_sync(0xffffffffu, s, o);
    if (lane == 0) g_csq[row] = s;
}

// ---------------- per-row symmetric int8 quantization ------------------------
// One warp per 512-float row: scale = 127/max|x|; stores int8 row + inv scale.
__global__ void quant_rows(const float* __restrict__ X,
                           signed char* __restrict__ Q,
                           float* __restrict__ InvS) {
    int row  = blockIdx.x * 8 + (threadIdx.x >> 5);
    int lane = threadIdx.x & 31;
    const float4* p = (const float4*)(X + (size_t)row * DDIM) + lane * 4;
    float4 v[4];
    float mx = 0.f;
#pragma unroll
    for (int i = 0; i < 4; i++) {
        v[i] = p[i];
        mx = fmaxf(mx, fmaxf(fmaxf(fabsf(v[i].x), fabsf(v[i].y)),
                             fmaxf(fabsf(v[i].z), fabsf(v[i].w))));
    }
#pragma unroll
    for (int o = 16; o; o >>= 1) mx = fmaxf(mx, __shfl_xor_sync(0xffffffffu, mx, o));
    float scale = (mx > 0.f) ? 127.f / mx : 0.f;
    if (lane == 0) InvS[row] = (mx > 0.f) ? mx / 127.f : 0.f;
    uint32_t w[4];
#pragma unroll
    for (int i = 0; i < 4; i++) {
        int q0 = __float2int_rn(v[i].x * scale);
        int q1 = __float2int_rn(v[i].y * scale);
        int q2 = __float2int_rn(v[i].z * scale);
        int q3 = __float2int_rn(v[i].w * scale);
        w[i] = (uint32_t)(q0 & 0xFF) | ((uint32_t)(q1 & 0xFF) << 8)
             | ((uint32_t)(q2 & 0xFF) << 16) | ((uint32_t)(q3 & 0xFF) << 24);
    }
    *(uint4*)(Q + (size_t)row * DDIM + lane * 16) = make_uint4(w[0], w[1], w[2], w[3]);
}

// ---------------- fp32 -> bf16 hi/lo split ----------------------------------
__global__ void splithl_kernel(const float* __restrict__ X,
                               __nv_bfloat16* __restrict__ Hi,
                               __nv_bfloat16* __restrict__ Lo) {
    int i = blockIdx.x * blockDim.x + threadIdx.x;
    float4 v = ((const float4*)X)[i];
    float f[4] = {v.x, v.y, v.z, v.w};
    __nv_bfloat16 h[4], l[4];
#pragma unroll
    for (int j = 0; j < 4; j++) {
        h[j] = __float2bfloat16(f[j]);
        l[j] = __float2bfloat16(f[j] - __bfloat162float(h[j]));
    }
    ((uint2*)Hi)[i] = *(uint2*)h;
    ((uint2*)Lo)[i] = *(uint2*)l;
}

// ---------------- bf16x3 HMMA GEMM (NT) + bias: C = A*B^T + b ----------------
#define G3_SMEM 65536

__global__ __launch_bounds__(256) void gemm3_nt_bias(
    const __nv_bfloat16* __restrict__ Ah, const __nv_bfloat16* __restrict__ Al,
    const __nv_bfloat16* __restrict__ Bh, const __nv_bfloat16* __restrict__ Bl,
    const float* __restrict__ bias, float* __restrict__ Out)
{
    extern __shared__ __align__(1024) char smem[];
    const int tid  = threadIdx.x;
    const int lane = tid & 31;
    const int wid  = tid >> 5;
    const int wm   = wid >> 2;
    const int wn   = wid & 3;
    const int m0   = blockIdx.x * 128;
    const int n0   = blockIdx.y * 128;
    const uint32_t sAh = smem_u32(smem);
    const uint32_t sAl = sAh + 16384;
    const uint32_t sBh = sAh + 32768;
    const uint32_t sBl = sAh + 49152;
    const int lb = lane & 15;

    float acc[4][4][4];
#pragma unroll
    for (int a = 0; a < 4; a++)
#pragma unroll
        for (int b = 0; b < 4; b++)
#pragma unroll
            for (int c = 0; c < 4; c++) acc[a][b][c] = 0.f;

    for (int ch = 0; ch < 8; ++ch) {
        const int k0 = ch << 6;
#pragma unroll
        for (int j = 0; j < 4; j++) {
            int u = tid + j * 256;
            int r = u >> 3, c16 = u & 7;
            uint32_t so = swz((uint32_t)(r * 128 + c16 * 16));
            size_t ga = (size_t)(m0 + r) * DDIM + k0 + c16 * 8;
            size_t gb = (size_t)(n0 + r) * DDIM + k0 + c16 * 8;
            cp16(sAh + so, Ah + ga);
            cp16(sAl + so, Al + ga);
            cp16(sBh + so, Bh + gb);
            cp16(sBl + so, Bl + gb);
        }
        CP_COMMIT();
        CP_WAIT(0);
        __syncthreads();

#pragma unroll
        for (int p = 0; p < 3; p++) {
            const uint32_t abase = (p == 2) ? sAl : sAh;
            const uint32_t bbase = (p == 1) ? sBl : sBh;
#pragma unroll
            for (int kk = 0; kk < 4; kk++) {
                uint32_t afr[4][4];
#pragma unroll
                for (int im = 0; im < 4; im++) {
                    uint32_t off = (uint32_t)((wm * 64 + im * 16 + (lane & 15)) * 128
                                              + kk * 32 + (lane >> 4) * 16);
                    ldsm_x4(afr[im][0], afr[im][1], afr[im][2], afr[im][3],
                            abase + swz(off));
                }
#pragma unroll
                for (int in = 0; in < 4; in++) {
                    uint32_t off = (uint32_t)((wn * 32 + in * 8 + (lb & 7)) * 128
                                              + kk * 32 + ((lb >> 3) & 1) * 16);
                    uint32_t b0, b1;
                    ldsm_x2(b0, b1, bbase + swz(off));
#pragma unroll
                    for (int im = 0; im < 4; im++)
                        mma16816(acc[im][in], afr[im], b0, b1);
                }
            }
        }
        __syncthreads();
    }

#pragma unroll
    for (int in = 0; in < 4; in++) {
        const int col = n0 + wn * 32 + in * 8 + (lane & 3) * 2;
        const float b0 = __ldg(bias + col);
        const float b1 = __ldg(bias + col + 1);
#pragma unroll
        for (int im = 0; im < 4; im++) {
            const int r0 = m0 + wm * 64 + im * 16 + (lane >> 2);
            float2 o0 = make_float2(acc[im][in][0] + b0, acc[im][in][1] + b1);
            float2 o1 = make_float2(acc[im][in][2] + b0, acc[im][in][3] + b1);
            *(float2*)(Out + (size_t)r0 * DDIM + col)       = o0;
            *(float2*)(Out + (size_t)(r0 + 8) * DDIM + col) = o1;
        }
    }
}

// ---------------- int8 mma distance GEMM + per-token top candidates ----------
// CTA: 128 tokens. A resident in SMEM: 4 chunk tiles of [128 rows][128 B] int8
// (64 KB). Loops 64 N-tiles of 256 codes; B (32 KB/chunk) double-buffered.
// 8 warps = 2(M) x 4(N); warp tile 64x64; mma m16n8k32 s8 -> s32.
// dist(t,k) = csq[k] - 2 * acc * inv_sr[t] * inv_sc[k]
#define VQ_SMEM (65536 + 2 * 32768)

__global__ __launch_bounds__(256) void vq_topk() {
    extern __shared__ __align__(1024) char smem[];
    const int tid  = threadIdx.x;
    const int lane = tid & 31;
    const int wid  = tid >> 5;
    const int wm   = wid >> 2;        // 0..1
    const int wn   = wid & 3;         // 0..3
    const int m0   = blockIdx.x * 128;
    const uint32_t sA = smem_u32(smem);
    const uint32_t sB = sA + 65536;

    // preload resident A (128 x 512 int8 = 64 KB; 4 chunks of [128][128B])
#pragma unroll 4
    for (int u = tid; u < 4096; u += 256) {
        int chunk = u >> 10, rem = u & 1023;
        int r = rem >> 3, c16 = rem & 7;
        cp16(sA + chunk * 16384 + swz((uint32_t)(r * 128 + c16 * 16)),
             g_res_i8 + (size_t)(m0 + r) * DDIM + chunk * 128 + c16 * 16);
    }
    CP_COMMIT();
    // first B chunk (n-tile 0, k-chunk 0): 256 rows x 128 B
#pragma unroll
    for (int j = 0; j < 8; j++) {
        int u = tid + j * 256;
        int r = u >> 3, c16 = u & 7;
        cp16(sB + swz((uint32_t)(r * 128 + c16 * 16)),
             g_cb_i8 + (size_t)r * DDIM + c16 * 16);
    }
    CP_COMMIT();

    // per-token inverse scales for this thread's 8 token rows
    float sr0[4], sr1[4];
#pragma unroll
    for (int im = 0; im < 4; im++) {
        int t0 = m0 + wm * 64 + im * 16 + (lane >> 2);
        sr0[im] = __ldg(g_inv_sr + t0);
        sr1[im] = __ldg(g_inv_sr + t0 + 8);
    }

    unsigned long long top[8][3];
#pragma unroll
    for (int i = 0; i < 8; i++)
#pragma unroll
        for (int j = 0; j < 3; j++) top[i][j] = ~0ULL;

    int acc[4][8][4];
#pragma unroll
    for (int a = 0; a < 4; a++)
#pragma unroll
        for (int b = 0; b < 8; b++)
#pragma unroll
            for (int c = 0; c < 4; c++) acc[a][b][c] = 0;

    const int lb = lane & 15;

    for (int it = 0; it < 256; ++it) {                  // 64 n-tiles x 4 k-chunks
        if (it + 1 < 256) {
            const int nx  = it + 1;
            const int nn0 = (nx >> 2) << 8;
            const int nch = nx & 3;
            const uint32_t bb = sB + (uint32_t)(nx & 1) * 32768;
#pragma unroll
            for (int j = 0; j < 8; j++) {
                int u = tid + j * 256;
                int r = u >> 3, c16 = u & 7;
                cp16(bb + swz((uint32_t)(r * 128 + c16 * 16)),
                     g_cb_i8 + (size_t)(nn0 + r) * DDIM + nch * 128 + c16 * 16);
            }
            CP_COMMIT();
            CP_WAIT(1);
        } else {
            CP_WAIT(0);
        }
        __syncthreads();

        const int ch = it & 3;
        const uint32_t abase = sA + (uint32_t)ch * 16384;
        const uint32_t bbase = sB + (uint32_t)(it & 1) * 32768;
#pragma unroll
        for (int kk = 0; kk < 4; kk++) {                // 32 bytes (k=32) each
            uint32_t afr[4][4];
#pragma unroll
            for (int im = 0; im < 4; im++) {
                uint32_t off = (uint32_t)((wm * 64 + im * 16 + (lane & 15)) * 128
                                          + kk * 32 + (lane >> 4) * 16);
                ldsm_x4(afr[im][0], afr[im][1], afr[im][2], afr[im][3],
                        abase + swz(off));
            }
#pragma unroll
            for (int in = 0; in < 8; in++) {
                uint32_t off = (uint32_t)((wn * 64 + in * 8 + (lb & 7)) * 128
                                          + kk * 32 + ((lb >> 3) & 1) * 16);
                uint32_t b0, b1;
                ldsm_x2(b0, b1, bbase + swz(off));
#pragma unroll
                for (int im = 0; im < 4; im++)
                    mma16832(acc[im][in], afr[im], b0, b1);
            }
        }

        if (ch == 3) {                                  // fold N-tile into top-3
            const int n0 = (it >> 2) << 8;
#pragma unroll
            for (int in = 0; in < 8; in++) {
                const int ncol = n0 + wn * 64 + in * 8 + (lane & 3) * 2;
                const float cs0 = __ldg(g_csq + ncol);
                const float cs1 = __ldg(g_csq + ncol + 1);
                const float f0  = -2.f * __ldg(g_inv_sc + ncol);
                const float f1  = -2.f * __ldg(g_inv_sc + ncol + 1);
#pragma unroll
                for (int im = 0; im < 4; im++) {
                    float d;
                    d = fmaf((float)acc[im][in][0], f0 * sr0[im], cs0);
                    ins3(top[im * 2],     pk(d, ncol));
                    d = fmaf((float)acc[im][in][1], f1 * sr0[im], cs1);
                    ins3(top[im * 2],     pk(d, ncol + 1));
                    d = fmaf((float)acc[im][in][2], f0 * sr1[im], cs0);
                    ins3(top[im * 2 + 1], pk(d, ncol));
                    d = fmaf((float)acc[im][in][3], f1 * sr1[im], cs1);
                    ins3(top[im * 2 + 1], pk(d, ncol + 1));
                    acc[im][in][0] = 0; acc[im][in][1] = 0;
                    acc[im][in][2] = 0; acc[im][in][3] = 0;
                }
            }
        }
        __syncthreads();
    }

    // merge per-lane top-3 lists (16 lane-slots per token) via smem (reuse A)
    unsigned long long* cand = (unsigned long long*)smem;
#pragma unroll
    for (int im = 0; im < 4; im++)
#pragma unroll
        for (int h = 0; h < 2; h++) {
            int token = wm * 64 + im * 16 + h * 8 + (lane >> 2);
            int slot  = wn * 4 + (lane & 3);
            size_t base = ((size_t)token * 16 + slot) * 3;
            cand[base + 0] = top[im * 2 + h][0];
            cand[base + 1] = top[im * 2 + h][1];
            cand[base + 2] = top[im * 2 + h][2];
        }
    __syncthreads();
    if (tid < 128) {
        unsigned long long best[8];
#pragma unroll
        for (int j = 0; j < 8; j++) best[j] = ~0ULL;
        const unsigned long long* p = cand + (size_t)tid * 48;
        for (int i = 0; i < 48; i++) {
            unsigned long long k = p[i];
            if (k < best[7]) {
                int pos = 7;
                while (pos > 0 && k < best[pos - 1]) { best[pos] = best[pos - 1]; pos--; }
                best[pos] = k;
            }
        }
        const int t = m0 + tid;
#pragma unroll
        for (int j = 0; j < 8; j++)
            g_cand[j][t] = (int)(best[j] & 0xffffffffu);
    }
}

// ---------------- exact fp32 refine over 8 candidates ------------------------
__global__ void refine_kernel(const float* __restrict__ C) {
    const int wid  = threadIdx.x >> 5;
    const int lane = threadIdx.x & 31;
    const int t = blockIdx.x * 8 + wid;
    int cd[8];
#pragma unroll
    for (int j = 0; j < 8; j++) cd[j] = g_cand[j][t];
    const float4* r4 = (const float4*)(g_res + (size_t)t * DDIM);
    float s[8] = {0.f, 0.f, 0.f, 0.f, 0.f, 0.f, 0.f, 0.f};
#pragma unroll
    for (int i = 0; i < 4; i++) {
        float4 rv = r4[lane + i * 32];
#pragma unroll
        for (int j = 0; j < 8; j++) {
            float4 cv = __ldg((const float4*)(C + (size_t)cd[j] * DDIM) + lane + i * 32);
            s[j] = fmaf(rv.x, cv.x, s[j]); s[j] = fmaf(rv.y, cv.y, s[j]);
            s[j] = fmaf(rv.z, cv.z, s[j]); s[j] = fmaf(rv.w, cv.w, s[j]);
        }
    }
#pragma unroll
    for (int j = 0; j < 8; j++)
#pragma unroll
        for (int o = 16; o; o >>= 1) s[j] += __shfl_xor_sync(0xffffffffu, s[j], o);
    if (lane == 0) {
        float bd = __int_as_float(0x7f800000);
        int   bi = 0x7fffffff;
#pragma unroll
        for (int j = 0; j < 8; j++) {
            float d = fmaf(-2.f, s[j], g_csq[cd[j]]);
            if (d < bd || (d == bd && cd[j] < bi)) { bd = d; bi = cd[j]; }
        }
        g_idx[t] = bi;
    }
}

// ---------------- gather + accumulate + residual update ---------------------
__global__ void vq_apply(const float* __restrict__ C, int stage) {
    int t  = blockIdx.x;
    int id = g_idx[t];
    const float4* c = (const float4*)(C + (size_t)id * DDIM);
    float4* q = (float4*)(g_qsum + (size_t)t * DDIM);
    float4* r = (float4*)(g_res  + (size_t)t * DDIM);
    int i = threadIdx.x;
    float4 cv = c[i];
    if (stage == 0) {
        q[i] = cv;
        float4 rv = r[i];
        rv.x -= cv.x; rv.y -= cv.y; rv.z -= cv.z; rv.w -= cv.w;
        r[i] = rv;
    } else {
        float4 qv = q[i];
        qv.x += cv.x; qv.y += cv.y; qv.z += cv.z; qv.w += cv.w;
        q[i] = qv;
    }
}

// ---------------- launch ----------------------------------------------------
extern "C" void kernel_launch(void* const* d_in, const int* in_sizes, int n_in,
                              void* d_out, int out_size)
{
    const float* x     = (const float*)d_in[0];
    const float* enc_w = (const float*)d_in[1];
    const float* enc_b = (const float*)d_in[2];
    const float* cb    = (const float*)d_in[3];
    const float* dec_w = (const float*)d_in[4];
    const float* dec_b = (const float*)d_in[5];
    float* out = (float*)d_out;

    float *res_p, *q_p, *isr_p, *isc_p;
    signed char *ri8_p, *ci8_p;
    __nv_bfloat16 *ah_p, *al_p, *wh_p, *wl_p;
    cudaGetSymbolAddress((void**)&res_p, g_res);
    cudaGetSymbolAddress((void**)&q_p,   g_qsum);
    cudaGetSymbolAddress((void**)&isr_p, g_inv_sr);
    cudaGetSymbolAddress((void**)&isc_p, g_inv_sc);
    cudaGetSymbolAddress((void**)&ri8_p, g_res_i8);
    cudaGetSymbolAddress((void**)&ci8_p, g_cb_i8);
    cudaGetSymbolAddress((void**)&ah_p,  g_a_hi);
    cudaGetSymbolAddress((void**)&al_p,  g_a_lo);
    cudaGetSymbolAddress((void**)&wh_p,  g_w_hi);
    cudaGetSymbolAddress((void**)&wl_p,  g_w_lo);

    cudaFuncSetAttribute(vq_topk, cudaFuncAttributeMaxDynamicSharedMemorySize, VQ_SMEM);
    cudaFuncSetAttribute(gemm3_nt_bias, cudaFuncAttributeMaxDynamicSharedMemorySize, G3_SMEM);

    csq_kernel<<<KCB / 8, 256>>>(cb);
    quant_rows<<<KCB / 8, 256>>>(cb, ci8_p, isc_p);

    // encoder: bf16x3 tensor GEMM -> fp32 z (g_res)
    splithl_kernel<<<(DDIM * DDIM / 4) / 256, 256>>>(enc_w, wh_p, wl_p);
    splithl_kernel<<<(TTOK * DDIM / 4) / 256, 256>>>(x, ah_p, al_p);
    gemm3_nt_bias<<<dim3(TTOK / 128, DDIM / 128), 256, G3_SMEM>>>(
        ah_p, al_p, wh_p, wl_p, enc_b, res_p);

    // stage 0
    quant_rows<<<TTOK / 8, 256>>>(res_p, ri8_p, isr_p);
    vq_topk<<<TTOK / 128, 256, VQ_SMEM>>>();
    refine_kernel<<<TTOK / 8, 256>>>(cb);
    vq_apply<<<TTOK, 128>>>(cb, 0);

    // stage 1
    quant_rows<<<TTOK / 8, 256>>>(res_p, ri8_p, isr_p);
    vq_topk<<<TTOK / 128, 256, VQ_SMEM>>>();
    refine_kernel<<<TTOK / 8, 256>>>(cb);
    vq_apply<<<TTOK, 128>>>(cb, 1);

    // decoder: bf16x3 tensor GEMM on q_sum
    splithl_kernel<<<(DDIM * DDIM / 4) / 256, 256>>>(dec_w, wh_p, wl_p);
    splithl_kernel<<<(TTOK * DDIM / 4) / 256, 256>>>(q_p, ah_p, al_p);
    gemm3_nt_bias<<<dim3(TTOK / 128, DDIM / 128), 256, G3_SMEM>>>(
        ah_p, al_p, wh_p, wl_p, dec_b, out);
}

// round 15
// speedup vs baseline: 2.1287x; 2.1287x over previous
#include <cuda_runtime.h>
#include <cuda_bf16.h>
#include <cstdint>

#define TTOK 16384
#define DDIM 512
#define KCB  16384

// ---------------- scratch (device globals: no allocation allowed) ----------
__device__ float g_res [TTOK * DDIM];
__device__ float g_qsum[TTOK * DDIM];
__device__ float g_csq [KCB];
__device__ int   g_idx [TTOK];
__device__ __nv_bfloat16 g_res_bf[TTOK * DDIM];
__device__ __nv_bfloat16 g_cb_bf [KCB * DDIM];
__device__ __nv_bfloat16 g_a_hi[TTOK * DDIM];   // activation hi/lo for enc/dec GEMM
__device__ __nv_bfloat16 g_a_lo[TTOK * DDIM];
__device__ __nv_bfloat16 g_w_hi[DDIM * DDIM];   // weight hi/lo
__device__ __nv_bfloat16 g_w_lo[DDIM * DDIM];
__device__ int g_cand[4][TTOK];

// ---------------- helpers ---------------------------------------------------
__device__ __forceinline__ unsigned fkey(float f) {
    unsigned u = __float_as_uint(f);
    return (u & 0x80000000u) ? ~u : (u | 0x80000000u);
}
__device__ __forceinline__ uint32_t swz(uint32_t off) {      // SW128 (Swizzle<3,4,3>)
    return off ^ (((off >> 7) & 7u) << 4);
}
__device__ __forceinline__ uint32_t smem_u32(const void* p) {
    uint32_t a;
    asm("{ .reg .u64 t; cvta.to.shared.u64 t, %1; cvt.u32.u64 %0, t; }"
        : "=r"(a) : "l"(p));
    return a;
}
__device__ __forceinline__ void cp16(uint32_t dst, const void* src) {
    asm volatile("cp.async.cg.shared.global [%0], [%1], 16;" :: "r"(dst), "l"(src));
}
#define CP_COMMIT()  asm volatile("cp.async.commit_group;" ::: "memory")
#define CP_WAIT(N)   asm volatile("cp.async.wait_group %0;" :: "n"(N) : "memory")

__device__ __forceinline__ void ldsm_x4(uint32_t& r0, uint32_t& r1,
                                        uint32_t& r2, uint32_t& r3, uint32_t a) {
    asm volatile("ldmatrix.sync.aligned.m8n8.x4.shared.b16 {%0,%1,%2,%3}, [%4];"
                 : "=r"(r0), "=r"(r1), "=r"(r2), "=r"(r3) : "r"(a));
}
__device__ __forceinline__ void ldsm_x2(uint32_t& r0, uint32_t& r1, uint32_t a) {
    asm volatile("ldmatrix.sync.aligned.m8n8.x2.shared.b16 {%0,%1}, [%2];"
                 : "=r"(r0), "=r"(r1) : "r"(a));
}
__device__ __forceinline__ void mma16816(float* c, const uint32_t* a,
                                         uint32_t b0, uint32_t b1) {
    asm volatile(
        "mma.sync.aligned.m16n8k16.row.col.f32.bf16.bf16.f32 "
        "{%0,%1,%2,%3}, {%4,%5,%6,%7}, {%8,%9}, {%0,%1,%2,%3};"
        : "+f"(c[0]), "+f"(c[1]), "+f"(c[2]), "+f"(c[3])
        : "r"(a[0]), "r"(a[1]), "r"(a[2]), "r"(a[3]), "r"(b0), "r"(b1));
}
__device__ __forceinline__ void ins3(unsigned long long* t, unsigned long long k) {
    if (k < t[2]) {
        if (k < t[1]) {
            t[2] = t[1];
            if (k < t[0]) { t[1] = t[0]; t[0] = k; } else t[1] = k;
        } else t[2] = k;
    }
}
__device__ __forceinline__ unsigned long long pk(float d, int idx) {
    return ((unsigned long long)fkey(d) << 32) | (unsigned)idx;
}

// ---------------- codebook prep: ||c||^2 + bf16 copy (one pass) -------------
__global__ void cb_prep(const float* __restrict__ C,
                        __nv_bfloat16* __restrict__ Cbf) {
    int row  = blockIdx.x * 8 + (threadIdx.x >> 5);
    int lane = threadIdx.x & 31;
    const float4* p = (const float4*)(C + (size_t)row * DDIM);
    uint2* ob = (uint2*)(Cbf + (size_t)row * DDIM);
    float s = 0.f;
#pragma unroll
    for (int i = 0; i < 4; i++) {
        float4 v = p[lane + (i << 5)];
        s = fmaf(v.x, v.x, s); s = fmaf(v.y, v.y, s);
        s = fmaf(v.z, v.z, s); s = fmaf(v.w, v.w, s);
        __nv_bfloat16 h[4];
        h[0] = __float2bfloat16(v.x); h[1] = __float2bfloat16(v.y);
        h[2] = __float2bfloat16(v.z); h[3] = __float2bfloat16(v.w);
        ob[lane + (i << 5)] = *(uint2*)h;
    }
#pragma unroll
    for (int o = 16; o; o >>= 1) s += __shfl_xor_sync(0xffffffffu, s, o);
    if (lane == 0) g_csq[row] = s;
}

// ---------------- fp32 -> bf16 hi/lo split ----------------------------------
__global__ void splithl_kernel(const float* __restrict__ X,
                               __nv_bfloat16* __restrict__ Hi,
                               __nv_bfloat16* __restrict__ Lo) {
    int i = blockIdx.x * blockDim.x + threadIdx.x;
    float4 v = ((const float4*)X)[i];
    float f[4] = {v.x, v.y, v.z, v.w};
    __nv_bfloat16 h[4], l[4];
#pragma unroll
    for (int j = 0; j < 4; j++) {
        h[j] = __float2bfloat16(f[j]);
        l[j] = __float2bfloat16(f[j] - __bfloat162float(h[j]));
    }
    ((uint2*)Hi)[i] = *(uint2*)h;
    ((uint2*)Lo)[i] = *(uint2*)l;
}

// ---------------- bf16x3 HMMA GEMM (NT) + bias: C = A*B^T + b ----------------
// A,B given as hi/lo bf16 pairs; accumulates Ah*Bh + Ah*Bl + Al*Bh in fp32.
// CTA tile 128x128, 8 warps (2x4), warp tile 64x32. K=512 in 8 chunks of 64.
#define G3_SMEM 65536

__global__ __launch_bounds__(256) void gemm3_nt_bias(
    const __nv_bfloat16* __restrict__ Ah, const __nv_bfloat16* __restrict__ Al,
    const __nv_bfloat16* __restrict__ Bh, const __nv_bfloat16* __restrict__ Bl,
    const float* __restrict__ bias, float* __restrict__ Out,
    __nv_bfloat16* __restrict__ Obf)
{
    extern __shared__ __align__(1024) char smem[];
    const int tid  = threadIdx.x;
    const int lane = tid & 31;
    const int wid  = tid >> 5;
    const int wm   = wid >> 2;
    const int wn   = wid & 3;
    const int m0   = blockIdx.x * 128;
    const int n0   = blockIdx.y * 128;
    const uint32_t sAh = smem_u32(smem);
    const uint32_t sAl = sAh + 16384;
    const uint32_t sBh = sAh + 32768;
    const uint32_t sBl = sAh + 49152;
    const int lb = lane & 15;

    float acc[4][4][4];
#pragma unroll
    for (int a = 0; a < 4; a++)
#pragma unroll
        for (int b = 0; b < 4; b++)
#pragma unroll
            for (int c = 0; c < 4; c++) acc[a][b][c] = 0.f;

    for (int ch = 0; ch < 8; ++ch) {
        const int k0 = ch << 6;
#pragma unroll
        for (int j = 0; j < 4; j++) {
            int u = tid + j * 256;
            int r = u >> 3, c16 = u & 7;
            uint32_t so = swz((uint32_t)(r * 128 + c16 * 16));
            size_t ga = (size_t)(m0 + r) * DDIM + k0 + c16 * 8;
            size_t gb = (size_t)(n0 + r) * DDIM + k0 + c16 * 8;
            cp16(sAh + so, Ah + ga);
            cp16(sAl + so, Al + ga);
            cp16(sBh + so, Bh + gb);
            cp16(sBl + so, Bl + gb);
        }
        CP_COMMIT();
        CP_WAIT(0);
        __syncthreads();

#pragma unroll
        for (int p = 0; p < 3; p++) {
            const uint32_t abase = (p == 2) ? sAl : sAh;
            const uint32_t bbase = (p == 1) ? sBl : sBh;
#pragma unroll
            for (int kk = 0; kk < 4; kk++) {
                uint32_t afr[4][4];
#pragma unroll
                for (int im = 0; im < 4; im++) {
                    uint32_t off = (uint32_t)((wm * 64 + im * 16 + (lane & 15)) * 128
                                              + kk * 32 + (lane >> 4) * 16);
                    ldsm_x4(afr[im][0], afr[im][1], afr[im][2], afr[im][3],
                            abase + swz(off));
                }
#pragma unroll
                for (int in = 0; in < 4; in++) {
                    uint32_t off = (uint32_t)((wn * 32 + in * 8 + (lb & 7)) * 128
                                              + kk * 32 + ((lb >> 3) & 1) * 16);
                    uint32_t b0, b1;
                    ldsm_x2(b0, b1, bbase + swz(off));
#pragma unroll
                    for (int im = 0; im < 4; im++)
                        mma16816(acc[im][in], afr[im], b0, b1);
                }
            }
        }
        __syncthreads();
    }

    // epilogue: bias + store fp32 (+ optional bf16 shadow)
#pragma unroll
    for (int in = 0; in < 4; in++) {
        const int col = n0 + wn * 32 + in * 8 + (lane & 3) * 2;
        const float b0 = __ldg(bias + col);
        const float b1 = __ldg(bias + col + 1);
#pragma unroll
        for (int im = 0; im < 4; im++) {
            const int r0 = m0 + wm * 64 + im * 16 + (lane >> 2);
            float2 o0 = make_float2(acc[im][in][0] + b0, acc[im][in][1] + b1);
            float2 o1 = make_float2(acc[im][in][2] + b0, acc[im][in][3] + b1);
            *(float2*)(Out + (size_t)r0 * DDIM + col)       = o0;
            *(float2*)(Out + (size_t)(r0 + 8) * DDIM + col) = o1;
            if (Obf) {
                __nv_bfloat16 h0[2] = {__float2bfloat16(o0.x), __float2bfloat16(o0.y)};
                __nv_bfloat16 h1[2] = {__float2bfloat16(o1.x), __float2bfloat16(o1.y)};
                *(uint32_t*)(Obf + (size_t)r0 * DDIM + col)       = *(uint32_t*)h0;
                *(uint32_t*)(Obf + (size_t)(r0 + 8) * DDIM + col) = *(uint32_t*)h1;
            }
        }
    }
}

// ---------------- bf16 mma.sync distance GEMM + per-token top candidates -----
// CTA: 128 tokens, A resident in SMEM (8 chunk tiles of [128][64] bf16, SW128).
// Loops 64 N-tiles of 256 codes; B (32KB/chunk) double-buffered via cp.async.
// 8 warps = 2(M) x 4(N); warp tile 64x64; mma m16n8k16 bf16->f32.
#define VQ_SMEM (131072 + 2 * 32768)

__global__ __launch_bounds__(256) void vq_topk() {
    extern __shared__ __align__(1024) char smem[];
    const int tid  = threadIdx.x;
    const int lane = tid & 31;
    const int wid  = tid >> 5;
    const int wm   = wid >> 2;        // 0..1
    const int wn   = wid & 3;         // 0..3
    const int m0   = blockIdx.x * 128;
    const uint32_t sA = smem_u32(smem);
    const uint32_t sB = sA + 131072;

    // preload resident A (128 x 512 bf16 = 128 KB)
#pragma unroll 4
    for (int u = tid; u < 8192; u += 256) {
        int chunk = u >> 10, rem = u & 1023;
        int r = rem >> 3, c16 = rem & 7;
        cp16(sA + chunk * 16384 + swz((uint32_t)(r * 128 + c16 * 16)),
             g_res_bf + (size_t)(m0 + r) * DDIM + chunk * 64 + c16 * 8);
    }
    CP_COMMIT();
    // first B chunk (n-tile 0, k-chunk 0): 256 rows x 64 cols
#pragma unroll
    for (int j = 0; j < 8; j++) {
        int u = tid + j * 256;
        int r = u >> 3, c16 = u & 7;
        cp16(sB + swz((uint32_t)(r * 128 + c16 * 16)),
             g_cb_bf + (size_t)r * DDIM + c16 * 8);
    }
    CP_COMMIT();

    unsigned long long top[8][3];
#pragma unroll
    for (int i = 0; i < 8; i++)
#pragma unroll
        for (int j = 0; j < 3; j++) top[i][j] = ~0ULL;

    float acc[4][8][4];
#pragma unroll
    for (int a = 0; a < 4; a++)
#pragma unroll
        for (int b = 0; b < 8; b++)
#pragma unroll
            for (int c = 0; c < 4; c++) acc[a][b][c] = 0.f;

    const int lb = lane & 15;

    for (int it = 0; it < 512; ++it) {                  // 64 n-tiles x 8 k-chunks
        if (it + 1 < 512) {
            const int nx  = it + 1;
            const int nn0 = (nx >> 3) << 8;
            const int nch = nx & 7;
            const uint32_t bb = sB + (uint32_t)(nx & 1) * 32768;
#pragma unroll
            for (int j = 0; j < 8; j++) {
                int u = tid + j * 256;
                int r = u >> 3, c16 = u & 7;
                cp16(bb + swz((uint32_t)(r * 128 + c16 * 16)),
                     g_cb_bf + (size_t)(nn0 + r) * DDIM + nch * 64 + c16 * 8);
            }
            CP_COMMIT();
            CP_WAIT(1);
        } else {
            CP_WAIT(0);
        }
        __syncthreads();

        const int ch = it & 7;
        const uint32_t abase = sA + (uint32_t)ch * 16384;
        const uint32_t bbase = sB + (uint32_t)(it & 1) * 32768;
#pragma unroll
        for (int kk = 0; kk < 4; kk++) {
            uint32_t afr[4][4];
#pragma unroll
            for (int im = 0; im < 4; im++) {
                uint32_t off = (uint32_t)((wm * 64 + im * 16 + (lane & 15)) * 128
                                          + kk * 32 + (lane >> 4) * 16);
                ldsm_x4(afr[im][0], afr[im][1], afr[im][2], afr[im][3],
                        abase + swz(off));
            }
#pragma unroll
            for (int in = 0; in < 8; in++) {
                uint32_t off = (uint32_t)((wn * 64 + in * 8 + (lb & 7)) * 128
                                          + kk * 32 + ((lb >> 3) & 1) * 16);
                uint32_t b0, b1;
                ldsm_x2(b0, b1, bbase + swz(off));
#pragma unroll
                for (int im = 0; im < 4; im++)
                    mma16816(acc[im][in], afr[im], b0, b1);
            }
        }

        if (ch == 7) {                                  // fold N-tile into top-3
            const int n0 = (it >> 3) << 8;
#pragma unroll
            for (int in = 0; in < 8; in++) {
                const int ncol = n0 + wn * 64 + in * 8 + (lane & 3) * 2;
                const float cs0 = __ldg(g_csq + ncol);
                const float cs1 = __ldg(g_csq + ncol + 1);
#pragma unroll
                for (int im = 0; im < 4; im++) {
                    float d;
                    d = fmaf(-2.f, acc[im][in][0], cs0); ins3(top[im * 2],     pk(d, ncol));
                    d = fmaf(-2.f, acc[im][in][1], cs1); ins3(top[im * 2],     pk(d, ncol + 1));
                    d = fmaf(-2.f, acc[im][in][2], cs0); ins3(top[im * 2 + 1], pk(d, ncol));
                    d = fmaf(-2.f, acc[im][in][3], cs1); ins3(top[im * 2 + 1], pk(d, ncol + 1));
                    acc[im][in][0] = 0.f; acc[im][in][1] = 0.f;
                    acc[im][in][2] = 0.f; acc[im][in][3] = 0.f;
                }
            }
        }
        __syncthreads();
    }

    // merge per-lane top-3 lists (16 lane-slots per token) via smem (reuse A)
    unsigned long long* cand = (unsigned long long*)smem;
#pragma unroll
    for (int im = 0; im < 4; im++)
#pragma unroll
        for (int h = 0; h < 2; h++) {
            int token = wm * 64 + im * 16 + h * 8 + (lane >> 2);
            int slot  = wn * 4 + (lane & 3);
            size_t base = ((size_t)token * 16 + slot) * 3;
            cand[base + 0] = top[im * 2 + h][0];
            cand[base + 1] = top[im * 2 + h][1];
            cand[base + 2] = top[im * 2 + h][2];
        }
    __syncthreads();
    if (tid < 128) {
        unsigned long long b0 = ~0ULL, b1 = ~0ULL, b2 = ~0ULL, b3 = ~0ULL;
        const unsigned long long* p = cand + (size_t)tid * 48;
        for (int i = 0; i < 48; i++) {
            unsigned long long k = p[i];
            if (k < b3) {
                if (k < b2) {
                    b3 = b2;
                    if (k < b1) {
                        b2 = b1;
                        if (k < b0) { b1 = b0; b0 = k; } else b1 = k;
                    } else b2 = k;
                } else b3 = k;
            }
        }
        const int t = m0 + tid;
        g_cand[0][t] = (int)(b0 & 0xffffffffu);
        g_cand[1][t] = (int)(b1 & 0xffffffffu);
        g_cand[2][t] = (int)(b2 & 0xffffffffu);
        g_cand[3][t] = (int)(b3 & 0xffffffffu);
    }
}

// ---------------- exact fp32 refine over 4 candidates ------------------------
__global__ void refine_kernel(const float* __restrict__ C) {
    const int wid  = threadIdx.x >> 5;
    const int lane = threadIdx.x & 31;
    const int t = blockIdx.x * 8 + wid;
    int cd[4];
#pragma unroll
    for (int j = 0; j < 4; j++) cd[j] = g_cand[j][t];
    const float4* r4 = (const float4*)(g_res + (size_t)t * DDIM);
    float s[4] = {0.f, 0.f, 0.f, 0.f};
#pragma unroll
    for (int i = 0; i < 4; i++) {
        float4 rv = r4[lane + i * 32];
#pragma unroll
        for (int j = 0; j < 4; j++) {
            float4 cv = __ldg((const float4*)(C + (size_t)cd[j] * DDIM) + lane + i * 32);
            s[j] = fmaf(rv.x, cv.x, s[j]); s[j] = fmaf(rv.y, cv.y, s[j]);
            s[j] = fmaf(rv.z, cv.z, s[j]); s[j] = fmaf(rv.w, cv.w, s[j]);
        }
    }
#pragma unroll
    for (int j = 0; j < 4; j++)
#pragma unroll
        for (int o = 16; o; o >>= 1) s[j] += __shfl_xor_sync(0xffffffffu, s[j], o);
    if (lane == 0) {
        float bd = __int_as_float(0x7f800000);
        int   bi = 0x7fffffff;
#pragma unroll
        for (int j = 0; j < 4; j++) {
            float d = fmaf(-2.f, s[j], g_csq[cd[j]]);
            if (d < bd || (d == bd && cd[j] < bi)) { bd = d; bi = cd[j]; }
        }
        g_idx[t] = bi;
    }
}

// ---------------- gather + accumulate + residual update ---------------------
__global__ void vq_apply(const float* __restrict__ C, int stage) {
    int t  = blockIdx.x;
    int id = g_idx[t];
    const float4* c = (const float4*)(C + (size_t)id * DDIM);
    float4* q = (float4*)(g_qsum + (size_t)t * DDIM);
    float4* r = (float4*)(g_res  + (size_t)t * DDIM);
    int i = threadIdx.x;
    float4 cv = c[i];
    if (stage == 0) {
        q[i] = cv;
        float4 rv = r[i];
        rv.x -= cv.x; rv.y -= cv.y; rv.z -= cv.z; rv.w -= cv.w;
        r[i] = rv;
        __nv_bfloat16 h[4];                         // bf16 shadow for stage-1 GEMM
        h[0] = __float2bfloat16(rv.x); h[1] = __float2bfloat16(rv.y);
        h[2] = __float2bfloat16(rv.z); h[3] = __float2bfloat16(rv.w);
        *((uint2*)(g_res_bf + (size_t)t * DDIM) + i) = *(uint2*)h;
    } else {
        float4 qv = q[i];
        qv.x += cv.x; qv.y += cv.y; qv.z += cv.z; qv.w += cv.w;
        q[i] = qv;
    }
}

// ---------------- launch ----------------------------------------------------
extern "C" void kernel_launch(void* const* d_in, const int* in_sizes, int n_in,
                              void* d_out, int out_size)
{
    const float* x     = (const float*)d_in[0];
    const float* enc_w = (const float*)d_in[1];
    const float* enc_b = (const float*)d_in[2];
    const float* cb    = (const float*)d_in[3];
    const float* dec_w = (const float*)d_in[4];
    const float* dec_b = (const float*)d_in[5];
    float* out = (float*)d_out;

    float *res_p, *q_p;
    __nv_bfloat16 *rb_p, *cbb_p, *ah_p, *al_p, *wh_p, *wl_p;
    cudaGetSymbolAddress((void**)&res_p, g_res);
    cudaGetSymbolAddress((void**)&q_p,   g_qsum);
    cudaGetSymbolAddress((void**)&rb_p,  g_res_bf);
    cudaGetSymbolAddress((void**)&cbb_p, g_cb_bf);
    cudaGetSymbolAddress((void**)&ah_p,  g_a_hi);
    cudaGetSymbolAddress((void**)&al_p,  g_a_lo);
    cudaGetSymbolAddress((void**)&wh_p,  g_w_hi);
    cudaGetSymbolAddress((void**)&wl_p,  g_w_lo);

    cudaFuncSetAttribute(vq_topk, cudaFuncAttributeMaxDynamicSharedMemorySize, VQ_SMEM);
    cudaFuncSetAttribute(gemm3_nt_bias, cudaFuncAttributeMaxDynamicSharedMemorySize, G3_SMEM);

    // codebook prep: csq + bf16 copy in one pass
    cb_prep<<<KCB / 8, 256>>>(cb, cbb_p);

    // encoder: bf16x3 tensor GEMM, emits fp32 z (g_res) + bf16 shadow
    splithl_kernel<<<(DDIM * DDIM / 4) / 256, 256>>>(enc_w, wh_p, wl_p);
    splithl_kernel<<<(TTOK * DDIM / 4) / 256, 256>>>(x, ah_p, al_p);
    gemm3_nt_bias<<<dim3(TTOK / 128, DDIM / 128), 256, G3_SMEM>>>(
        ah_p, al_p, wh_p, wl_p, enc_b, res_p, rb_p);

    // stage 0
    vq_topk<<<TTOK / 128, 256, VQ_SMEM>>>();
    refine_kernel<<<TTOK / 8, 256>>>(cb);
    vq_apply<<<TTOK, 128>>>(cb, 0);   // updates g_res and g_res_bf

    // stage 1
    vq_topk<<<TTOK / 128, 256, VQ_SMEM>>>();
    refine_kernel<<<TTOK / 8, 256>>>(cb);
    vq_apply<<<TTOK, 128>>>(cb, 1);

    // decoder: bf16x3 tensor GEMM on q_sum
    splithl_kernel<<<(DDIM * DDIM / 4) / 256, 256>>>(dec_w, wh_p, wl_p);
    splithl_kernel<<<(TTOK * DDIM / 4) / 256, 256>>>(q_p, ah_p, al_p);
    gemm3_nt_bias<<<dim3(TTOK / 128, DDIM / 128), 256, G3_SMEM>>>(
        ah_p, al_p, wh_p, wl_p, dec_b, out, nullptr);
}

// round 16
// speedup vs baseline: 2.1945x; 1.0309x over previous
#include <cuda_runtime.h>
#include <cuda_bf16.h>
#include <cstdint>

#define TTOK 16384
#define DDIM 512
#define KCB  16384
#define NRANGE 8                       // codebook ranges per token tile
#define RCODES (KCB / NRANGE)          // 2048 codes per range

// ---------------- scratch (device globals: no allocation allowed) ----------
__device__ float g_res [TTOK * DDIM];
__device__ float g_qsum[TTOK * DDIM];
__device__ float g_csq [KCB];
__device__ int   g_idx [TTOK];
__device__ __nv_bfloat16 g_res_bf[TTOK * DDIM];
__device__ __nv_bfloat16 g_cb_bf [KCB * DDIM];
__device__ __nv_bfloat16 g_a_hi[TTOK * DDIM];   // activation hi/lo for enc/dec GEMM
__device__ __nv_bfloat16 g_a_lo[TTOK * DDIM];
__device__ __nv_bfloat16 g_w_hi[DDIM * DDIM];   // weight hi/lo
__device__ __nv_bfloat16 g_w_lo[DDIM * DDIM];
__device__ unsigned long long g_keys[TTOK * NRANGE * 4];  // per-range top-4 keys
__device__ int g_cand[4][TTOK];

// ---------------- helpers ---------------------------------------------------
__device__ __forceinline__ unsigned fkey(float f) {
    unsigned u = __float_as_uint(f);
    return (u & 0x80000000u) ? ~u : (u | 0x80000000u);
}
__device__ __forceinline__ uint32_t swz(uint32_t off) {      // SW128 (Swizzle<3,4,3>)
    return off ^ (((off >> 7) & 7u) << 4);
}
__device__ __forceinline__ uint32_t smem_u32(const void* p) {
    uint32_t a;
    asm("{ .reg .u64 t; cvta.to.shared.u64 t, %1; cvt.u32.u64 %0, t; }"
        : "=r"(a) : "l"(p));
    return a;
}
__device__ __forceinline__ void cp16(uint32_t dst, const void* src) {
    asm volatile("cp.async.cg.shared.global [%0], [%1], 16;" :: "r"(dst), "l"(src));
}
#define CP_COMMIT()  asm volatile("cp.async.commit_group;" ::: "memory")
#define CP_WAIT(N)   asm volatile("cp.async.wait_group %0;" :: "n"(N) : "memory")

__device__ __forceinline__ void ldsm_x4(uint32_t& r0, uint32_t& r1,
                                        uint32_t& r2, uint32_t& r3, uint32_t a) {
    asm volatile("ldmatrix.sync.aligned.m8n8.x4.shared.b16 {%0,%1,%2,%3}, [%4];"
                 : "=r"(r0), "=r"(r1), "=r"(r2), "=r"(r3) : "r"(a));
}
__device__ __forceinline__ void ldsm_x2(uint32_t& r0, uint32_t& r1, uint32_t a) {
    asm volatile("ldmatrix.sync.aligned.m8n8.x2.shared.b16 {%0,%1}, [%2];"
                 : "=r"(r0), "=r"(r1) : "r"(a));
}
__device__ __forceinline__ void mma16816(float* c, const uint32_t* a,
                                         uint32_t b0, uint32_t b1) {
    asm volatile(
        "mma.sync.aligned.m16n8k16.row.col.f32.bf16.bf16.f32 "
        "{%0,%1,%2,%3}, {%4,%5,%6,%7}, {%8,%9}, {%0,%1,%2,%3};"
        : "+f"(c[0]), "+f"(c[1]), "+f"(c[2]), "+f"(c[3])
        : "r"(a[0]), "r"(a[1]), "r"(a[2]), "r"(a[3]), "r"(b0), "r"(b1));
}
__device__ __forceinline__ void ins3(unsigned long long* t, unsigned long long k) {
    if (k < t[2]) {
        if (k < t[1]) {
            t[2] = t[1];
            if (k < t[0]) { t[1] = t[0]; t[0] = k; } else t[1] = k;
        } else t[2] = k;
    }
}
__device__ __forceinline__ unsigned long long pk(float d, int idx) {
    return ((unsigned long long)fkey(d) << 32) | (unsigned)idx;
}

// ---------------- codebook prep: ||c||^2 + bf16 copy (one pass) -------------
__global__ void cb_prep(const float* __restrict__ C,
                        __nv_bfloat16* __restrict__ Cbf) {
    int row  = blockIdx.x * 8 + (threadIdx.x >> 5);
    int lane = threadIdx.x & 31;
    const float4* p = (const float4*)(C + (size_t)row * DDIM);
    uint2* ob = (uint2*)(Cbf + (size_t)row * DDIM);
    float s = 0.f;
#pragma unroll
    for (int i = 0; i < 4; i++) {
        float4 v = p[lane + (i << 5)];
        s = fmaf(v.x, v.x, s); s = fmaf(v.y, v.y, s);
        s = fmaf(v.z, v.z, s); s = fmaf(v.w, v.w, s);
        __nv_bfloat16 h[4];
        h[0] = __float2bfloat16(v.x); h[1] = __float2bfloat16(v.y);
        h[2] = __float2bfloat16(v.z); h[3] = __float2bfloat16(v.w);
        ob[lane + (i << 5)] = *(uint2*)h;
    }
#pragma unroll
    for (int o = 16; o; o >>= 1) s += __shfl_xor_sync(0xffffffffu, s, o);
    if (lane == 0) g_csq[row] = s;
}

// ---------------- fp32 -> bf16 hi/lo split ----------------------------------
__global__ void splithl_kernel(const float* __restrict__ X,
                               __nv_bfloat16* __restrict__ Hi,
                               __nv_bfloat16* __restrict__ Lo) {
    int i = blockIdx.x * blockDim.x + threadIdx.x;
    float4 v = ((const float4*)X)[i];
    float f[4] = {v.x, v.y, v.z, v.w};
    __nv_bfloat16 h[4], l[4];
#pragma unroll
    for (int j = 0; j < 4; j++) {
        h[j] = __float2bfloat16(f[j]);
        l[j] = __float2bfloat16(f[j] - __bfloat162float(h[j]));
    }
    ((uint2*)Hi)[i] = *(uint2*)h;
    ((uint2*)Lo)[i] = *(uint2*)l;
}

// ---------------- bf16x3 HMMA GEMM (NT) + bias: C = A*B^T + b ----------------
// A,B given as hi/lo bf16 pairs; accumulates Ah*Bh + Ah*Bl + Al*Bh in fp32.
// CTA tile 128x128, 8 warps (2x4), warp tile 64x32. K=512 in 8 chunks of 64.
#define G3_SMEM 65536

__global__ __launch_bounds__(256) void gemm3_nt_bias(
    const __nv_bfloat16* __restrict__ Ah, const __nv_bfloat16* __restrict__ Al,
    const __nv_bfloat16* __restrict__ Bh, const __nv_bfloat16* __restrict__ Bl,
    const float* __restrict__ bias, float* __restrict__ Out,
    __nv_bfloat16* __restrict__ Obf)
{
    extern __shared__ __align__(1024) char smem[];
    const int tid  = threadIdx.x;
    const int lane = tid & 31;
    const int wid  = tid >> 5;
    const int wm   = wid >> 2;
    const int wn   = wid & 3;
    const int m0   = blockIdx.x * 128;
    const int n0   = blockIdx.y * 128;
    const uint32_t sAh = smem_u32(smem);
    const uint32_t sAl = sAh + 16384;
    const uint32_t sBh = sAh + 32768;
    const uint32_t sBl = sAh + 49152;
    const int lb = lane & 15;

    float acc[4][4][4];
#pragma unroll
    for (int a = 0; a < 4; a++)
#pragma unroll
        for (int b = 0; b < 4; b++)
#pragma unroll
            for (int c = 0; c < 4; c++) acc[a][b][c] = 0.f;

    for (int ch = 0; ch < 8; ++ch) {
        const int k0 = ch << 6;
#pragma unroll
        for (int j = 0; j < 4; j++) {
            int u = tid + j * 256;
            int r = u >> 3, c16 = u & 7;
            uint32_t so = swz((uint32_t)(r * 128 + c16 * 16));
            size_t ga = (size_t)(m0 + r) * DDIM + k0 + c16 * 8;
            size_t gb = (size_t)(n0 + r) * DDIM + k0 + c16 * 8;
            cp16(sAh + so, Ah + ga);
            cp16(sAl + so, Al + ga);
            cp16(sBh + so, Bh + gb);
            cp16(sBl + so, Bl + gb);
        }
        CP_COMMIT();
        CP_WAIT(0);
        __syncthreads();

#pragma unroll
        for (int p = 0; p < 3; p++) {
            const uint32_t abase = (p == 2) ? sAl : sAh;
            const uint32_t bbase = (p == 1) ? sBl : sBh;
#pragma unroll
            for (int kk = 0; kk < 4; kk++) {
                uint32_t afr[4][4];
#pragma unroll
                for (int im = 0; im < 4; im++) {
                    uint32_t off = (uint32_t)((wm * 64 + im * 16 + (lane & 15)) * 128
                                              + kk * 32 + (lane >> 4) * 16);
                    ldsm_x4(afr[im][0], afr[im][1], afr[im][2], afr[im][3],
                            abase + swz(off));
                }
#pragma unroll
                for (int in = 0; in < 4; in++) {
                    uint32_t off = (uint32_t)((wn * 32 + in * 8 + (lb & 7)) * 128
                                              + kk * 32 + ((lb >> 3) & 1) * 16);
                    uint32_t b0, b1;
                    ldsm_x2(b0, b1, bbase + swz(off));
#pragma unroll
                    for (int im = 0; im < 4; im++)
                        mma16816(acc[im][in], afr[im], b0, b1);
                }
            }
        }
        __syncthreads();
    }

    // epilogue: bias + store fp32 (+ optional bf16 shadow)
#pragma unroll
    for (int in = 0; in < 4; in++) {
        const int col = n0 + wn * 32 + in * 8 + (lane & 3) * 2;
        const float b0 = __ldg(bias + col);
        const float b1 = __ldg(bias + col + 1);
#pragma unroll
        for (int im = 0; im < 4; im++) {
            const int r0 = m0 + wm * 64 + im * 16 + (lane >> 2);
            float2 o0 = make_float2(acc[im][in][0] + b0, acc[im][in][1] + b1);
            float2 o1 = make_float2(acc[im][in][2] + b0, acc[im][in][3] + b1);
            *(float2*)(Out + (size_t)r0 * DDIM + col)       = o0;
            *(float2*)(Out + (size_t)(r0 + 8) * DDIM + col) = o1;
            if (Obf) {
                __nv_bfloat16 h0[2] = {__float2bfloat16(o0.x), __float2bfloat16(o0.y)};
                __nv_bfloat16 h1[2] = {__float2bfloat16(o1.x), __float2bfloat16(o1.y)};
                *(uint32_t*)(Obf + (size_t)r0 * DDIM + col)       = *(uint32_t*)h0;
                *(uint32_t*)(Obf + (size_t)(r0 + 8) * DDIM + col) = *(uint32_t*)h1;
            }
        }
    }
}

// ---------------- bf16 mma.sync distance GEMM + per-range top candidates -----
// Grid (128, 8): blockIdx.x = 128-token tile, blockIdx.y = 2048-code range.
// A resident in SMEM (8 chunk tiles of [128][64] bf16, SW128).
// Loops 8 N-tiles of 256 codes; B (32KB/chunk) double-buffered via cp.async.
// 8 warps = 2(M) x 4(N); warp tile 64x64; mma m16n8k16 bf16->f32.
// Emits per-token per-range top-4 packed (dist|idx) keys to g_keys.
#define VQ_SMEM (131072 + 2 * 32768)

__global__ __launch_bounds__(256) void vq_topk() {
    extern __shared__ __align__(1024) char smem[];
    const int tid  = threadIdx.x;
    const int lane = tid & 31;
    const int wid  = tid >> 5;
    const int wm   = wid >> 2;        // 0..1
    const int wn   = wid & 3;         // 0..3
    const int m0   = blockIdx.x * 128;
    const int nb   = blockIdx.y * RCODES;
    const uint32_t sA = smem_u32(smem);
    const uint32_t sB = sA + 131072;

    // preload resident A (128 x 512 bf16 = 128 KB)
#pragma unroll 4
    for (int u = tid; u < 8192; u += 256) {
        int chunk = u >> 10, rem = u & 1023;
        int r = rem >> 3, c16 = rem & 7;
        cp16(sA + chunk * 16384 + swz((uint32_t)(r * 128 + c16 * 16)),
             g_res_bf + (size_t)(m0 + r) * DDIM + chunk * 64 + c16 * 8);
    }
    CP_COMMIT();
    // first B chunk (n-tile 0 of range, k-chunk 0): 256 rows x 64 cols
#pragma unroll
    for (int j = 0; j < 8; j++) {
        int u = tid + j * 256;
        int r = u >> 3, c16 = u & 7;
        cp16(sB + swz((uint32_t)(r * 128 + c16 * 16)),
             g_cb_bf + (size_t)(nb + r) * DDIM + c16 * 8);
    }
    CP_COMMIT();

    unsigned long long top[8][3];
#pragma unroll
    for (int i = 0; i < 8; i++)
#pragma unroll
        for (int j = 0; j < 3; j++) top[i][j] = ~0ULL;

    float acc[4][8][4];
#pragma unroll
    for (int a = 0; a < 4; a++)
#pragma unroll
        for (int b = 0; b < 8; b++)
#pragma unroll
            for (int c = 0; c < 4; c++) acc[a][b][c] = 0.f;

    const int lb = lane & 15;

    for (int it = 0; it < 8 * (RCODES / 256); ++it) {   // 8 n-tiles x 8 k-chunks
        if (it + 1 < 8 * (RCODES / 256)) {
            const int nx  = it + 1;
            const int nn0 = nb + ((nx >> 3) << 8);
            const int nch = nx & 7;
            const uint32_t bb = sB + (uint32_t)(nx & 1) * 32768;
#pragma unroll
            for (int j = 0; j < 8; j++) {
                int u = tid + j * 256;
                int r = u >> 3, c16 = u & 7;
                cp16(bb + swz((uint32_t)(r * 128 + c16 * 16)),
                     g_cb_bf + (size_t)(nn0 + r) * DDIM + nch * 64 + c16 * 8);
            }
            CP_COMMIT();
            CP_WAIT(1);
        } else {
            CP_WAIT(0);
        }
        __syncthreads();

        const int ch = it & 7;
        const uint32_t abase = sA + (uint32_t)ch * 16384;
        const uint32_t bbase = sB + (uint32_t)(it & 1) * 32768;
#pragma unroll
        for (int kk = 0; kk < 4; kk++) {
            uint32_t afr[4][4];
#pragma unroll
            for (int im = 0; im < 4; im++) {
                uint32_t off = (uint32_t)((wm * 64 + im * 16 + (lane & 15)) * 128
                                          + kk * 32 + (lane >> 4) * 16);
                ldsm_x4(afr[im][0], afr[im][1], afr[im][2], afr[im][3],
                        abase + swz(off));
            }
#pragma unroll
            for (int in = 0; in < 8; in++) {
                uint32_t off = (uint32_t)((wn * 64 + in * 8 + (lb & 7)) * 128
                                          + kk * 32 + ((lb >> 3) & 1) * 16);
                uint32_t b0, b1;
                ldsm_x2(b0, b1, bbase + swz(off));
#pragma unroll
                for (int im = 0; im < 4; im++)
                    mma16816(acc[im][in], afr[im], b0, b1);
            }
        }

        if (ch == 7) {                                  // fold N-tile into top-3
            const int n0 = nb + ((it >> 3) << 8);
#pragma unroll
            for (int in = 0; in < 8; in++) {
                const int ncol = n0 + wn * 64 + in * 8 + (lane & 3) * 2;
                const float cs0 = __ldg(g_csq + ncol);
                const float cs1 = __ldg(g_csq + ncol + 1);
#pragma unroll
                for (int im = 0; im < 4; im++) {
                    float d;
                    d = fmaf(-2.f, acc[im][in][0], cs0); ins3(top[im * 2],     pk(d, ncol));
                    d = fmaf(-2.f, acc[im][in][1], cs1); ins3(top[im * 2],     pk(d, ncol + 1));
                    d = fmaf(-2.f, acc[im][in][2], cs0); ins3(top[im * 2 + 1], pk(d, ncol));
                    d = fmaf(-2.f, acc[im][in][3], cs1); ins3(top[im * 2 + 1], pk(d, ncol + 1));
                    acc[im][in][0] = 0.f; acc[im][in][1] = 0.f;
                    acc[im][in][2] = 0.f; acc[im][in][3] = 0.f;
                }
            }
        }
        __syncthreads();
    }

    // merge per-lane top-3 lists (16 lane-slots per token) via smem (reuse A)
    unsigned long long* cand = (unsigned long long*)smem;
#pragma unroll
    for (int im = 0; im < 4; im++)
#pragma unroll
        for (int h = 0; h < 2; h++) {
            int token = wm * 64 + im * 16 + h * 8 + (lane >> 2);
            int slot  = wn * 4 + (lane & 3);
            size_t base = ((size_t)token * 16 + slot) * 3;
            cand[base + 0] = top[im * 2 + h][0];
            cand[base + 1] = top[im * 2 + h][1];
            cand[base + 2] = top[im * 2 + h][2];
        }
    __syncthreads();
    if (tid < 128) {
        unsigned long long b0 = ~0ULL, b1 = ~0ULL, b2 = ~0ULL, b3 = ~0ULL;
        const unsigned long long* p = cand + (size_t)tid * 48;
        for (int i = 0; i < 48; i++) {
            unsigned long long k = p[i];
            if (k < b3) {
                if (k < b2) {
                    b3 = b2;
                    if (k < b1) {
                        b2 = b1;
                        if (k < b0) { b1 = b0; b0 = k; } else b1 = k;
                    } else b2 = k;
                } else b3 = k;
            }
        }
        unsigned long long* out = g_keys
            + ((size_t)(m0 + tid) * NRANGE + blockIdx.y) * 4;
        out[0] = b0; out[1] = b1; out[2] = b2; out[3] = b3;
    }
}

// ---------------- merge per-range keys -> global top-4 candidates ------------
__global__ void merge_kernel() {
    int t = blockIdx.x * 256 + threadIdx.x;
    const unsigned long long* p = g_keys + (size_t)t * (NRANGE * 4);
    unsigned long long b0 = ~0ULL, b1 = ~0ULL, b2 = ~0ULL, b3 = ~0ULL;
#pragma unroll
    for (int i = 0; i < NRANGE * 4; i++) {
        unsigned long long k = p[i];
        if (k < b3) {
            if (k < b2) {
                b3 = b2;
                if (k < b1) {
                    b2 = b1;
                    if (k < b0) { b1 = b0; b0 = k; } else b1 = k;
                } else b2 = k;
            } else b3 = k;
        }
    }
    g_cand[0][t] = (int)(b0 & 0xffffffffu);
    g_cand[1][t] = (int)(b1 & 0xffffffffu);
    g_cand[2][t] = (int)(b2 & 0xffffffffu);
    g_cand[3][t] = (int)(b3 & 0xffffffffu);
}

// ---------------- exact fp32 refine over 4 candidates ------------------------
__global__ void refine_kernel(const float* __restrict__ C) {
    const int wid  = threadIdx.x >> 5;
    const int lane = threadIdx.x & 31;
    const int t = blockIdx.x * 8 + wid;
    int cd[4];
#pragma unroll
    for (int j = 0; j < 4; j++) cd[j] = g_cand[j][t];
    const float4* r4 = (const float4*)(g_res + (size_t)t * DDIM);
    float s[4] = {0.f, 0.f, 0.f, 0.f};
#pragma unroll
    for (int i = 0; i < 4; i++) {
        float4 rv = r4[lane + i * 32];
#pragma unroll
        for (int j = 0; j < 4; j++) {
            float4 cv = __ldg((const float4*)(C + (size_t)cd[j] * DDIM) + lane + i * 32);
            s[j] = fmaf(rv.x, cv.x, s[j]); s[j] = fmaf(rv.y, cv.y, s[j]);
            s[j] = fmaf(rv.z, cv.z, s[j]); s[j] = fmaf(rv.w, cv.w, s[j]);
        }
    }
#pragma unroll
    for (int j = 0; j < 4; j++)
#pragma unroll
        for (int o = 16; o; o >>= 1) s[j] += __shfl_xor_sync(0xffffffffu, s[j], o);
    if (lane == 0) {
        float bd = __int_as_float(0x7f800000);
        int   bi = 0x7fffffff;
#pragma unroll
        for (int j = 0; j < 4; j++) {
            float d = fmaf(-2.f, s[j], g_csq[cd[j]]);
            if (d < bd || (d == bd && cd[j] < bi)) { bd = d; bi = cd[j]; }
        }
        g_idx[t] = bi;
    }
}

// ---------------- gather + accumulate + residual update ---------------------
__global__ void vq_apply(const float* __restrict__ C, int stage) {
    int t  = blockIdx.x;
    int id = g_idx[t];
    const float4* c = (const float4*)(C + (size_t)id * DDIM);
    float4* q = (float4*)(g_qsum + (size_t)t * DDIM);
    float4* r = (float4*)(g_res  + (size_t)t * DDIM);
    int i = threadIdx.x;
    float4 cv = c[i];
    if (stage == 0) {
        q[i] = cv;
        float4 rv = r[i];
        rv.x -= cv.x; rv.y -= cv.y; rv.z -= cv.z; rv.w -= cv.w;
        r[i] = rv;
        __nv_bfloat16 h[4];                         // bf16 shadow for stage-1 GEMM
        h[0] = __float2bfloat16(rv.x); h[1] = __float2bfloat16(rv.y);
        h[2] = __float2bfloat16(rv.z); h[3] = __float2bfloat16(rv.w);
        *((uint2*)(g_res_bf + (size_t)t * DDIM) + i) = *(uint2*)h;
    } else {
        float4 qv = q[i];
        qv.x += cv.x; qv.y += cv.y; qv.z += cv.z; qv.w += cv.w;
        q[i] = qv;
    }
}

// ---------------- launch ----------------------------------------------------
extern "C" void kernel_launch(void* const* d_in, const int* in_sizes, int n_in,
                              void* d_out, int out_size)
{
    const float* x     = (const float*)d_in[0];
    const float* enc_w = (const float*)d_in[1];
    const float* enc_b = (const float*)d_in[2];
    const float* cb    = (const float*)d_in[3];
    const float* dec_w = (const float*)d_in[4];
    const float* dec_b = (const float*)d_in[5];
    float* out = (float*)d_out;

    float *res_p, *q_p;
    __nv_bfloat16 *rb_p, *cbb_p, *ah_p, *al_p, *wh_p, *wl_p;
    cudaGetSymbolAddress((void**)&res_p, g_res);
    cudaGetSymbolAddress((void**)&q_p,   g_qsum);
    cudaGetSymbolAddress((void**)&rb_p,  g_res_bf);
    cudaGetSymbolAddress((void**)&cbb_p, g_cb_bf);
    cudaGetSymbolAddress((void**)&ah_p,  g_a_hi);
    cudaGetSymbolAddress((void**)&al_p,  g_a_lo);
    cudaGetSymbolAddress((void**)&wh_p,  g_w_hi);
    cudaGetSymbolAddress((void**)&wl_p,  g_w_lo);

    cudaFuncSetAttribute(vq_topk, cudaFuncAttributeMaxDynamicSharedMemorySize, VQ_SMEM);
    cudaFuncSetAttribute(gemm3_nt_bias, cudaFuncAttributeMaxDynamicSharedMemorySize, G3_SMEM);

    // codebook prep: csq + bf16 copy in one pass
    cb_prep<<<KCB / 8, 256>>>(cb, cbb_p);

    // encoder: bf16x3 tensor GEMM, emits fp32 z (g_res) + bf16 shadow
    splithl_kernel<<<(DDIM * DDIM / 4) / 256, 256>>>(enc_w, wh_p, wl_p);
    splithl_kernel<<<(TTOK * DDIM / 4) / 256, 256>>>(x, ah_p, al_p);
    gemm3_nt_bias<<<dim3(TTOK / 128, DDIM / 128), 256, G3_SMEM>>>(
        ah_p, al_p, wh_p, wl_p, enc_b, res_p, rb_p);

    // stage 0
    vq_topk<<<dim3(TTOK / 128, NRANGE), 256, VQ_SMEM>>>();
    merge_kernel<<<TTOK / 256, 256>>>();
    refine_kernel<<<TTOK / 8, 256>>>(cb);
    vq_apply<<<TTOK, 128>>>(cb, 0);   // updates g_res and g_res_bf

    // stage 1
    vq_topk<<<dim3(TTOK / 128, NRANGE), 256, VQ_SMEM>>>();
    merge_kernel<<<TTOK / 256, 256>>>();
    refine_kernel<<<TTOK / 8, 256>>>(cb);
    vq_apply<<<TTOK, 128>>>(cb, 1);

    // decoder: bf16x3 tensor GEMM on q_sum
    splithl_kernel<<<(DDIM * DDIM / 4) / 256, 256>>>(dec_w, wh_p, wl_p);
    splithl_kernel<<<(TTOK * DDIM / 4) / 256, 256>>>(q_p, ah_p, al_p);
    gemm3_nt_bias<<<dim3(TTOK / 128, DDIM / 128), 256, G3_SMEM>>>(
        ah_p, al_p, wh_p, wl_p, dec_b, out, nullptr);
}

// round 17
// speedup vs baseline: 2.2259x; 1.0143x over previous
#include <cuda_runtime.h>
#include <cuda_bf16.h>
#include <cstdint>

#define TTOK 16384
#define DDIM 512
#define KCB  16384
#define NRANGE 8                       // codebook ranges per token tile
#define RCODES (KCB / NRANGE)          // 2048 codes per range

// ---------------- scratch (device globals: no allocation allowed) ----------
__device__ float g_res [TTOK * DDIM];
__device__ float g_qsum[TTOK * DDIM];
__device__ float g_csq [KCB];
__device__ __nv_bfloat16 g_res_bf[TTOK * DDIM];
__device__ __nv_bfloat16 g_cb_bf [KCB * DDIM];
__device__ __nv_bfloat16 g_a_hi[TTOK * DDIM];   // activation hi/lo for enc/dec GEMM
__device__ __nv_bfloat16 g_a_lo[TTOK * DDIM];
__device__ __nv_bfloat16 g_w_hi[DDIM * DDIM];   // weight hi/lo
__device__ __nv_bfloat16 g_w_lo[DDIM * DDIM];
__device__ unsigned long long g_keys[TTOK * NRANGE * 4];  // per-range top-4 keys

// ---------------- helpers ---------------------------------------------------
__device__ __forceinline__ unsigned fkey(float f) {
    unsigned u = __float_as_uint(f);
    return (u & 0x80000000u) ? ~u : (u | 0x80000000u);
}
__device__ __forceinline__ uint32_t swz(uint32_t off) {      // SW128 (Swizzle<3,4,3>)
    return off ^ (((off >> 7) & 7u) << 4);
}
__device__ __forceinline__ uint32_t smem_u32(const void* p) {
    uint32_t a;
    asm("{ .reg .u64 t; cvta.to.shared.u64 t, %1; cvt.u32.u64 %0, t; }"
        : "=r"(a) : "l"(p));
    return a;
}
__device__ __forceinline__ void cp16(uint32_t dst, const void* src) {
    asm volatile("cp.async.cg.shared.global [%0], [%1], 16;" :: "r"(dst), "l"(src));
}
#define CP_COMMIT()  asm volatile("cp.async.commit_group;" ::: "memory")
#define CP_WAIT(N)   asm volatile("cp.async.wait_group %0;" :: "n"(N) : "memory")

__device__ __forceinline__ void ldsm_x4(uint32_t& r0, uint32_t& r1,
                                        uint32_t& r2, uint32_t& r3, uint32_t a) {
    asm volatile("ldmatrix.sync.aligned.m8n8.x4.shared.b16 {%0,%1,%2,%3}, [%4];"
                 : "=r"(r0), "=r"(r1), "=r"(r2), "=r"(r3) : "r"(a));
}
__device__ __forceinline__ void ldsm_x2(uint32_t& r0, uint32_t& r1, uint32_t a) {
    asm volatile("ldmatrix.sync.aligned.m8n8.x2.shared.b16 {%0,%1}, [%2];"
                 : "=r"(r0), "=r"(r1) : "r"(a));
}
__device__ __forceinline__ void mma16816(float* c, const uint32_t* a,
                                         uint32_t b0, uint32_t b1) {
    asm volatile(
        "mma.sync.aligned.m16n8k16.row.col.f32.bf16.bf16.f32 "
        "{%0,%1,%2,%3}, {%4,%5,%6,%7}, {%8,%9}, {%0,%1,%2,%3};"
        : "+f"(c[0]), "+f"(c[1]), "+f"(c[2]), "+f"(c[3])
        : "r"(a[0]), "r"(a[1]), "r"(a[2]), "r"(a[3]), "r"(b0), "r"(b1));
}
__device__ __forceinline__ void ins3(unsigned long long* t, unsigned long long k) {
    if (k < t[2]) {
        if (k < t[1]) {
            t[2] = t[1];
            if (k < t[0]) { t[1] = t[0]; t[0] = k; } else t[1] = k;
        } else t[2] = k;
    }
}
__device__ __forceinline__ unsigned long long pk(float d, int idx) {
    return ((unsigned long long)fkey(d) << 32) | (unsigned)idx;
}

// ---------------- codebook prep: ||c||^2 + bf16 copy (one pass) -------------
__global__ void cb_prep(const float* __restrict__ C,
                        __nv_bfloat16* __restrict__ Cbf) {
    int row  = blockIdx.x * 8 + (threadIdx.x >> 5);
    int lane = threadIdx.x & 31;
    const float4* p = (const float4*)(C + (size_t)row * DDIM);
    uint2* ob = (uint2*)(Cbf + (size_t)row * DDIM);
    float s = 0.f;
#pragma unroll
    for (int i = 0; i < 4; i++) {
        float4 v = p[lane + (i << 5)];
        s = fmaf(v.x, v.x, s); s = fmaf(v.y, v.y, s);
        s = fmaf(v.z, v.z, s); s = fmaf(v.w, v.w, s);
        __nv_bfloat16 h[4];
        h[0] = __float2bfloat16(v.x); h[1] = __float2bfloat16(v.y);
        h[2] = __float2bfloat16(v.z); h[3] = __float2bfloat16(v.w);
        ob[lane + (i << 5)] = *(uint2*)h;
    }
#pragma unroll
    for (int o = 16; o; o >>= 1) s += __shfl_xor_sync(0xffffffffu, s, o);
    if (lane == 0) g_csq[row] = s;
}

// ---------------- fp32 -> bf16 hi/lo split ----------------------------------
__global__ void splithl_kernel(const float* __restrict__ X,
                               __nv_bfloat16* __restrict__ Hi,
                               __nv_bfloat16* __restrict__ Lo) {
    int i = blockIdx.x * blockDim.x + threadIdx.x;
    float4 v = ((const float4*)X)[i];
    float f[4] = {v.x, v.y, v.z, v.w};
    __nv_bfloat16 h[4], l[4];
#pragma unroll
    for (int j = 0; j < 4; j++) {
        h[j] = __float2bfloat16(f[j]);
        l[j] = __float2bfloat16(f[j] - __bfloat162float(h[j]));
    }
    ((uint2*)Hi)[i] = *(uint2*)h;
    ((uint2*)Lo)[i] = *(uint2*)l;
}

// ---------------- bf16x3 HMMA GEMM (NT) + bias: C = A*B^T + b ----------------
// A,B given as hi/lo bf16 pairs; accumulates Ah*Bh + Ah*Bl + Al*Bh in fp32.
// CTA tile 128x128, 8 warps (2x4), warp tile 64x32. K=512 in 8 chunks of 64.
#define G3_SMEM 65536

__global__ __launch_bounds__(256) void gemm3_nt_bias(
    const __nv_bfloat16* __restrict__ Ah, const __nv_bfloat16* __restrict__ Al,
    const __nv_bfloat16* __restrict__ Bh, const __nv_bfloat16* __restrict__ Bl,
    const float* __restrict__ bias, float* __restrict__ Out,
    __nv_bfloat16* __restrict__ Obf)
{
    extern __shared__ __align__(1024) char smem[];
    const int tid  = threadIdx.x;
    const int lane = tid & 31;
    const int wid  = tid >> 5;
    const int wm   = wid >> 2;
    const int wn   = wid & 3;
    const int m0   = blockIdx.x * 128;
    const int n0   = blockIdx.y * 128;
    const uint32_t sAh = smem_u32(smem);
    const uint32_t sAl = sAh + 16384;
    const uint32_t sBh = sAh + 32768;
    const uint32_t sBl = sAh + 49152;
    const int lb = lane & 15;

    float acc[4][4][4];
#pragma unroll
    for (int a = 0; a < 4; a++)
#pragma unroll
        for (int b = 0; b < 4; b++)
#pragma unroll
            for (int c = 0; c < 4; c++) acc[a][b][c] = 0.f;

    for (int ch = 0; ch < 8; ++ch) {
        const int k0 = ch << 6;
#pragma unroll
        for (int j = 0; j < 4; j++) {
            int u = tid + j * 256;
            int r = u >> 3, c16 = u & 7;
            uint32_t so = swz((uint32_t)(r * 128 + c16 * 16));
            size_t ga = (size_t)(m0 + r) * DDIM + k0 + c16 * 8;
            size_t gb = (size_t)(n0 + r) * DDIM + k0 + c16 * 8;
            cp16(sAh + so, Ah + ga);
            cp16(sAl + so, Al + ga);
            cp16(sBh + so, Bh + gb);
            cp16(sBl + so, Bl + gb);
        }
        CP_COMMIT();
        CP_WAIT(0);
        __syncthreads();

#pragma unroll
        for (int p = 0; p < 3; p++) {
            const uint32_t abase = (p == 2) ? sAl : sAh;
            const uint32_t bbase = (p == 1) ? sBl : sBh;
#pragma unroll
            for (int kk = 0; kk < 4; kk++) {
                uint32_t afr[4][4];
#pragma unroll
                for (int im = 0; im < 4; im++) {
                    uint32_t off = (uint32_t)((wm * 64 + im * 16 + (lane & 15)) * 128
                                              + kk * 32 + (lane >> 4) * 16);
                    ldsm_x4(afr[im][0], afr[im][1], afr[im][2], afr[im][3],
                            abase + swz(off));
                }
#pragma unroll
                for (int in = 0; in < 4; in++) {
                    uint32_t off = (uint32_t)((wn * 32 + in * 8 + (lb & 7)) * 128
                                              + kk * 32 + ((lb >> 3) & 1) * 16);
                    uint32_t b0, b1;
                    ldsm_x2(b0, b1, bbase + swz(off));
#pragma unroll
                    for (int im = 0; im < 4; im++)
                        mma16816(acc[im][in], afr[im], b0, b1);
                }
            }
        }
        __syncthreads();
    }

    // epilogue: bias + store fp32 (+ optional bf16 shadow)
#pragma unroll
    for (int in = 0; in < 4; in++) {
        const int col = n0 + wn * 32 + in * 8 + (lane & 3) * 2;
        const float b0 = __ldg(bias + col);
        const float b1 = __ldg(bias + col + 1);
#pragma unroll
        for (int im = 0; im < 4; im++) {
            const int r0 = m0 + wm * 64 + im * 16 + (lane >> 2);
            float2 o0 = make_float2(acc[im][in][0] + b0, acc[im][in][1] + b1);
            float2 o1 = make_float2(acc[im][in][2] + b0, acc[im][in][3] + b1);
            *(float2*)(Out + (size_t)r0 * DDIM + col)       = o0;
            *(float2*)(Out + (size_t)(r0 + 8) * DDIM + col) = o1;
            if (Obf) {
                __nv_bfloat16 h0[2] = {__float2bfloat16(o0.x), __float2bfloat16(o0.y)};
                __nv_bfloat16 h1[2] = {__float2bfloat16(o1.x), __float2bfloat16(o1.y)};
                *(uint32_t*)(Obf + (size_t)r0 * DDIM + col)       = *(uint32_t*)h0;
                *(uint32_t*)(Obf + (size_t)(r0 + 8) * DDIM + col) = *(uint32_t*)h1;
            }
        }
    }
}

// ---------------- bf16 mma.sync distance GEMM + per-range top candidates -----
// Grid (128, 8): blockIdx.x = 128-token tile, blockIdx.y = 2048-code range.
// A resident in SMEM (8 chunk tiles of [128][64] bf16, SW128).
// Loops 8 N-tiles of 256 codes; B (32KB/chunk) double-buffered via cp.async.
// 8 warps = 2(M) x 4(N); warp tile 64x64; mma m16n8k16 bf16->f32.
// Emits per-token per-range top-4 packed (dist|idx) keys to g_keys.
#define VQ_SMEM (131072 + 2 * 32768)

__global__ __launch_bounds__(256) void vq_topk() {
    extern __shared__ __align__(1024) char smem[];
    const int tid  = threadIdx.x;
    const int lane = tid & 31;
    const int wid  = tid >> 5;
    const int wm   = wid >> 2;        // 0..1
    const int wn   = wid & 3;         // 0..3
    const int m0   = blockIdx.x * 128;
    const int nb   = blockIdx.y * RCODES;
    const uint32_t sA = smem_u32(smem);
    const uint32_t sB = sA + 131072;

    // preload resident A (128 x 512 bf16 = 128 KB)
#pragma unroll 4
    for (int u = tid; u < 8192; u += 256) {
        int chunk = u >> 10, rem = u & 1023;
        int r = rem >> 3, c16 = rem & 7;
        cp16(sA + chunk * 16384 + swz((uint32_t)(r * 128 + c16 * 16)),
             g_res_bf + (size_t)(m0 + r) * DDIM + chunk * 64 + c16 * 8);
    }
    CP_COMMIT();
    // first B chunk (n-tile 0 of range, k-chunk 0): 256 rows x 64 cols
#pragma unroll
    for (int j = 0; j < 8; j++) {
        int u = tid + j * 256;
        int r = u >> 3, c16 = u & 7;
        cp16(sB + swz((uint32_t)(r * 128 + c16 * 16)),
             g_cb_bf + (size_t)(nb + r) * DDIM + c16 * 8);
    }
    CP_COMMIT();

    unsigned long long top[8][3];
#pragma unroll
    for (int i = 0; i < 8; i++)
#pragma unroll
        for (int j = 0; j < 3; j++) top[i][j] = ~0ULL;

    float acc[4][8][4];
#pragma unroll
    for (int a = 0; a < 4; a++)
#pragma unroll
        for (int b = 0; b < 8; b++)
#pragma unroll
            for (int c = 0; c < 4; c++) acc[a][b][c] = 0.f;

    const int lb = lane & 15;

    for (int it = 0; it < 8 * (RCODES / 256); ++it) {   // 8 n-tiles x 8 k-chunks
        if (it + 1 < 8 * (RCODES / 256)) {
            const int nx  = it + 1;
            const int nn0 = nb + ((nx >> 3) << 8);
            const int nch = nx & 7;
            const uint32_t bb = sB + (uint32_t)(nx & 1) * 32768;
#pragma unroll
            for (int j = 0; j < 8; j++) {
                int u = tid + j * 256;
                int r = u >> 3, c16 = u & 7;
                cp16(bb + swz((uint32_t)(r * 128 + c16 * 16)),
                     g_cb_bf + (size_t)(nn0 + r) * DDIM + nch * 64 + c16 * 8);
            }
            CP_COMMIT();
            CP_WAIT(1);
        } else {
            CP_WAIT(0);
        }
        __syncthreads();

        const int ch = it & 7;
        const uint32_t abase = sA + (uint32_t)ch * 16384;
        const uint32_t bbase = sB + (uint32_t)(it & 1) * 32768;
#pragma unroll
        for (int kk = 0; kk < 4; kk++) {
            uint32_t afr[4][4];
#pragma unroll
            for (int im = 0; im < 4; im++) {
                uint32_t off = (uint32_t)((wm * 64 + im * 16 + (lane & 15)) * 128
                                          + kk * 32 + (lane >> 4) * 16);
                ldsm_x4(afr[im][0], afr[im][1], afr[im][2], afr[im][3],
                        abase + swz(off));
            }
#pragma unroll
            for (int in = 0; in < 8; in++) {
                uint32_t off = (uint32_t)((wn * 64 + in * 8 + (lb & 7)) * 128
                                          + kk * 32 + ((lb >> 3) & 1) * 16);
                uint32_t b0, b1;
                ldsm_x2(b0, b1, bbase + swz(off));
#pragma unroll
                for (int im = 0; im < 4; im++)
                    mma16816(acc[im][in], afr[im], b0, b1);
            }
        }

        if (ch == 7) {                                  // fold N-tile into top-3
            const int n0 = nb + ((it >> 3) << 8);
#pragma unroll
            for (int in = 0; in < 8; in++) {
                const int ncol = n0 + wn * 64 + in * 8 + (lane & 3) * 2;
                const float cs0 = __ldg(g_csq + ncol);
                const float cs1 = __ldg(g_csq + ncol + 1);
#pragma unroll
                for (int im = 0; im < 4; im++) {
                    float d;
                    d = fmaf(-2.f, acc[im][in][0], cs0); ins3(top[im * 2],     pk(d, ncol));
                    d = fmaf(-2.f, acc[im][in][1], cs1); ins3(top[im * 2],     pk(d, ncol + 1));
                    d = fmaf(-2.f, acc[im][in][2], cs0); ins3(top[im * 2 + 1], pk(d, ncol));
                    d = fmaf(-2.f, acc[im][in][3], cs1); ins3(top[im * 2 + 1], pk(d, ncol + 1));
                    acc[im][in][0] = 0.f; acc[im][in][1] = 0.f;
                    acc[im][in][2] = 0.f; acc[im][in][3] = 0.f;
                }
            }
        }
        __syncthreads();
    }

    // merge per-lane top-3 lists (16 lane-slots per token) via smem (reuse A)
    unsigned long long* cand = (unsigned long long*)smem;
#pragma unroll
    for (int im = 0; im < 4; im++)
#pragma unroll
        for (int h = 0; h < 2; h++) {
            int token = wm * 64 + im * 16 + h * 8 + (lane >> 2);
            int slot  = wn * 4 + (lane & 3);
            size_t base = ((size_t)token * 16 + slot) * 3;
            cand[base + 0] = top[im * 2 + h][0];
            cand[base + 1] = top[im * 2 + h][1];
            cand[base + 2] = top[im * 2 + h][2];
        }
    __syncthreads();
    if (tid < 128) {
        unsigned long long b0 = ~0ULL, b1 = ~0ULL, b2 = ~0ULL, b3 = ~0ULL;
        const unsigned long long* p = cand + (size_t)tid * 48;
        for (int i = 0; i < 48; i++) {
            unsigned long long k = p[i];
            if (k < b3) {
                if (k < b2) {
                    b3 = b2;
                    if (k < b1) {
                        b2 = b1;
                        if (k < b0) { b1 = b0; b0 = k; } else b1 = k;
                    } else b2 = k;
                } else b3 = k;
            }
        }
        unsigned long long* out = g_keys
            + ((size_t)(m0 + tid) * NRANGE + blockIdx.y) * 4;
        out[0] = b0; out[1] = b1; out[2] = b2; out[3] = b3;
    }
}

// ---------------- fused merge + exact refine + apply -------------------------
// 1 warp per token. 32 lanes load the token's 32 per-range keys; 4 warp-min
// rounds select the global top-4 (identical semantics to the old merge).
// Exact fp32 distances over the 4 candidates pick the argmin; then the warp
// applies the code vector: stage 0 updates res (reusing in-register fragments)
// + qsum + bf16 shadow; stage 1 updates qsum and emits its hi/lo split for
// the decoder GEMM (replacing the separate splithl pass).
__global__ void refine_apply(const float* __restrict__ C, int stage) {
    const int wid  = threadIdx.x >> 5;
    const int lane = threadIdx.x & 31;
    const int t = blockIdx.x * 8 + wid;

    // merge: 32 keys -> top-4
    unsigned long long k = g_keys[(size_t)t * (NRANGE * 4) + lane];
    int cd[4];
#pragma unroll
    for (int j = 0; j < 4; j++) {
        unsigned long long m = k;
#pragma unroll
        for (int o = 16; o; o >>= 1) {
            unsigned long long v = __shfl_xor_sync(0xffffffffu, m, o);
            m = (v < m) ? v : m;
        }
        cd[j] = (int)(m & 0xffffffffu);
        if (k == m) k = ~0ULL;                       // keys unique; exclude winner
    }

    // exact fp32 distances over candidates (residual row kept in registers)
    const float4* r4 = (const float4*)(g_res + (size_t)t * DDIM);
    float4 rv[4];
    float s[4] = {0.f, 0.f, 0.f, 0.f};
#pragma unroll
    for (int i = 0; i < 4; i++) {
        rv[i] = r4[lane + i * 32];
#pragma unroll
        for (int j = 0; j < 4; j++) {
            float4 cv = __ldg((const float4*)(C + (size_t)cd[j] * DDIM) + lane + i * 32);
            s[j] = fmaf(rv[i].x, cv.x, s[j]); s[j] = fmaf(rv[i].y, cv.y, s[j]);
            s[j] = fmaf(rv[i].z, cv.z, s[j]); s[j] = fmaf(rv[i].w, cv.w, s[j]);
        }
    }
#pragma unroll
    for (int j = 0; j < 4; j++)
#pragma unroll
        for (int o = 16; o; o >>= 1) s[j] += __shfl_xor_sync(0xffffffffu, s[j], o);
    // all lanes hold identical sums -> all compute the same argmin
    float bd = __int_as_float(0x7f800000);
    int   bi = 0x7fffffff;
#pragma unroll
    for (int j = 0; j < 4; j++) {
        float d = fmaf(-2.f, s[j], g_csq[cd[j]]);
        if (d < bd || (d == bd && cd[j] < bi)) { bd = d; bi = cd[j]; }
    }

    // apply
    const float4* c4 = (const float4*)(C + (size_t)bi * DDIM);
    float4* q4 = (float4*)(g_qsum + (size_t)t * DDIM);
#pragma unroll
    for (int i = 0; i < 4; i++) {
        const int e = lane + i * 32;
        float4 cv = __ldg(c4 + e);
        if (stage == 0) {
            q4[e] = cv;
            float4 nr;
            nr.x = rv[i].x - cv.x; nr.y = rv[i].y - cv.y;
            nr.z = rv[i].z - cv.z; nr.w = rv[i].w - cv.w;
            ((float4*)(g_res + (size_t)t * DDIM))[e] = nr;
            __nv_bfloat16 h[4];                      // bf16 shadow for stage-1 GEMM
            h[0] = __float2bfloat16(nr.x); h[1] = __float2bfloat16(nr.y);
            h[2] = __float2bfloat16(nr.z); h[3] = __float2bfloat16(nr.w);
            *((uint2*)(g_res_bf + (size_t)t * DDIM) + e) = *(uint2*)h;
        } else {
            float4 qv = q4[e];
            qv.x += cv.x; qv.y += cv.y; qv.z += cv.z; qv.w += cv.w;
            q4[e] = qv;
            float f[4] = {qv.x, qv.y, qv.z, qv.w};   // hi/lo split for decoder GEMM
            __nv_bfloat16 h[4], l[4];
#pragma unroll
            for (int j = 0; j < 4; j++) {
                h[j] = __float2bfloat16(f[j]);
                l[j] = __float2bfloat16(f[j] - __bfloat162float(h[j]));
            }
            *((uint2*)(g_a_hi + (size_t)t * DDIM) + e) = *(uint2*)h;
            *((uint2*)(g_a_lo + (size_t)t * DDIM) + e) = *(uint2*)l;
        }
    }
}

// ---------------- launch ----------------------------------------------------
extern "C" void kernel_launch(void* const* d_in, const int* in_sizes, int n_in,
                              void* d_out, int out_size)
{
    const float* x     = (const float*)d_in[0];
    const float* enc_w = (const float*)d_in[1];
    const float* enc_b = (const float*)d_in[2];
    const float* cb    = (const float*)d_in[3];
    const float* dec_w = (const float*)d_in[4];
    const float* dec_b = (const float*)d_in[5];
    float* out = (float*)d_out;

    float *res_p;
    __nv_bfloat16 *rb_p, *cbb_p, *ah_p, *al_p, *wh_p, *wl_p;
    cudaGetSymbolAddress((void**)&res_p, g_res);
    cudaGetSymbolAddress((void**)&rb_p,  g_res_bf);
    cudaGetSymbolAddress((void**)&cbb_p, g_cb_bf);
    cudaGetSymbolAddress((void**)&ah_p,  g_a_hi);
    cudaGetSymbolAddress((void**)&al_p,  g_a_lo);
    cudaGetSymbolAddress((void**)&wh_p,  g_w_hi);
    cudaGetSymbolAddress((void**)&wl_p,  g_w_lo);

    cudaFuncSetAttribute(vq_topk, cudaFuncAttributeMaxDynamicSharedMemorySize, VQ_SMEM);
    cudaFuncSetAttribute(gemm3_nt_bias, cudaFuncAttributeMaxDynamicSharedMemorySize, G3_SMEM);

    // codebook prep: csq + bf16 copy in one pass
    cb_prep<<<KCB / 8, 256>>>(cb, cbb_p);

    // encoder: bf16x3 tensor GEMM, emits fp32 z (g_res) + bf16 shadow
    splithl_kernel<<<(DDIM * DDIM / 4) / 256, 256>>>(enc_w, wh_p, wl_p);
    splithl_kernel<<<(TTOK * DDIM / 4) / 256, 256>>>(x, ah_p, al_p);
    gemm3_nt_bias<<<dim3(TTOK / 128, DDIM / 128), 256, G3_SMEM>>>(
        ah_p, al_p, wh_p, wl_p, enc_b, res_p, rb_p);

    // stage 0: scan + fused merge/refine/apply (updates g_res, g_qsum, shadow)
    vq_topk<<<dim3(TTOK / 128, NRANGE), 256, VQ_SMEM>>>();
    refine_apply<<<TTOK / 8, 256>>>(cb, 0);

    // stage 1: scan + fused tail (updates g_qsum, emits decoder hi/lo input)
    vq_topk<<<dim3(TTOK / 128, NRANGE), 256, VQ_SMEM>>>();
    refine_apply<<<TTOK / 8, 256>>>(cb, 1);

    // decoder: bf16x3 tensor GEMM on q_sum (hi/lo emitted by refine_apply)
    splithl_kernel<<<(DDIM * DDIM / 4) / 256, 256>>>(dec_w, wh_p, wl_p);
    gemm3_nt_bias<<<dim3(TTOK / 128, DDIM / 128), 256, G3_SMEM>>>(
        ah_p, al_p, wh_p, wl_p, dec_b, out, nullptr);
}